// round 3
// baseline (speedup 1.0000x reference)
#include <cuda_runtime.h>

#define DD 768
#define NR 24          // DD / 32
#define NE 64          // NUM_ELEMS
#define MAXB 64

// scratch (no allocations allowed)
__device__ int   g_parent_seq[MAXB * NE];
__device__ float g_style_proj[MAXB * DD];

// ---------------------------------------------------------------------------
// setup: style projection (B x D) and parent_seq init
// ---------------------------------------------------------------------------
__global__ void setup_kernel(const float* __restrict__ sv,
                             const float* __restrict__ sw,
                             const float* __restrict__ sb, int B) {
    int b = blockIdx.x;
    if (b == 0) {
        for (int i = threadIdx.x; i < B * NE; i += blockDim.x)
            g_parent_seq[i] = -1;
    }
    float s0 = sv[b * 4 + 0], s1 = sv[b * 4 + 1];
    float s2 = sv[b * 4 + 2], s3 = sv[b * 4 + 3];
    for (int d = threadIdx.x; d < DD; d += blockDim.x) {
        g_style_proj[b * DD + d] =
            s0 * sw[0 * DD + d] + s1 * sw[1 * DD + d] +
            s2 * sw[2 * DD + d] + s3 * sw[3 * DD + d] + sb[d];
    }
}

// ---------------------------------------------------------------------------
// scan: parent_seq[b,e] = max s with panel at (b,s), element index e
// ---------------------------------------------------------------------------
__global__ void scan_kernel(const int* __restrict__ types,
                            const int* __restrict__ eidx,
                            int S, int total) {
    int i = blockIdx.x * blockDim.x + threadIdx.x;
    if (i >= total) return;
    if (types[i] == 1) {
        int b = i / S;
        int s = i - b * S;
        atomicMax(&g_parent_seq[b * NE + eidx[i]], s);
    }
}

// ---------------------------------------------------------------------------
// fused main kernel: one warp per token
// ---------------------------------------------------------------------------
__device__ __forceinline__ void warp_feats(
    int tk, int b, int lane,
    const int* __restrict__ types, const int* __restrict__ eidx,
    const int* __restrict__ pidx,
    const float* __restrict__ type_emb, const float* __restrict__ index_emb,
    const float* __restrict__ parent_emb,
    const float* __restrict__ ln_g, const float* __restrict__ ln_b,
    float* f) {
    const float* te = type_emb + types[tk] * DD;
    const float* ie = index_emb + eidx[tk] * DD;
    const float* pe = parent_emb + pidx[tk] * DD;
    const float* sp = g_style_proj + b * DD;
    float sum = 0.f, sq = 0.f;
#pragma unroll
    for (int r = 0; r < NR; r++) {
        int d = lane + 32 * r;
        float x = te[d] + ie[d] + pe[d] + sp[d];
        f[r] = x;
        sum += x;
        sq += x * x;
    }
#pragma unroll
    for (int o = 16; o; o >>= 1) {
        sum += __shfl_xor_sync(0xffffffffu, sum, o);
        sq  += __shfl_xor_sync(0xffffffffu, sq, o);
    }
    float mean = sum * (1.0f / DD);
    float var  = sq * (1.0f / DD) - mean * mean;
    float rstd = rsqrtf(var + 1e-5f);
#pragma unroll
    for (int r = 0; r < NR; r++) {
        int d = lane + 32 * r;
        f[r] = (f[r] - mean) * rstd * ln_g[d] + ln_b[d];
    }
}

__device__ __forceinline__ void reduce8(float* a) {
#pragma unroll
    for (int o = 16; o; o >>= 1) {
#pragma unroll
        for (int j = 0; j < 8; j++) a[j] += __shfl_xor_sync(0xffffffffu, a[j], o);
    }
}

__device__ __forceinline__ void reduce4(float* a) {
#pragma unroll
    for (int o = 16; o; o >>= 1) {
#pragma unroll
        for (int j = 0; j < 4; j++) a[j] += __shfl_xor_sync(0xffffffffu, a[j], o);
    }
}

__global__ void __launch_bounds__(256)
main_kernel(const int* __restrict__ types, const int* __restrict__ eidx,
            const int* __restrict__ pidx,
            const float* __restrict__ type_emb,
            const float* __restrict__ index_emb,
            const float* __restrict__ parent_emb,
            const float* __restrict__ ln_g, const float* __restrict__ ln_b,
            const float* __restrict__ panel_w, const float* __restrict__ panel_b,
            const float* __restrict__ dialog_w, const float* __restrict__ dialog_b,
            const float* __restrict__ char_w, const float* __restrict__ char_b,
            float* __restrict__ out_panel, float* __restrict__ out_dialog,
            float* __restrict__ out_char, int Bv, int Sv) {
    int wid  = (blockIdx.x * blockDim.x + threadIdx.x) >> 5;
    int lane = threadIdx.x & 31;
    int total = Bv * Sv;
    if (wid >= total) return;
    int tk = wid;
    int b  = tk / Sv;
    int t  = types[tk];

    float* po = out_panel  + tk * 8;
    float* dо = out_dialog + tk * 8;
    float* co = out_char   + tk * 4;
    const float4 z4 = make_float4(0.f, 0.f, 0.f, 0.f);

    if (t == 0) {
        if (lane == 0) {
            *(float4*)po = z4; *(float4*)(po + 4) = z4;
            *(float4*)dо = z4; *(float4*)(dо + 4) = z4;
            *(float4*)co = z4;
        }
        return;
    }

    float f[NR];
    warp_feats(tk, b, lane, types, eidx, pidx, type_emb, index_emb, parent_emb,
               ln_g, ln_b, f);

    if (t == 1) {  // PANEL head
        float a[8] = {0.f, 0.f, 0.f, 0.f, 0.f, 0.f, 0.f, 0.f};
#pragma unroll
        for (int r = 0; r < NR; r++) {
            int d = lane + 32 * r;
            float4 w0 = *(const float4*)(panel_w + d * 8);
            float4 w1 = *(const float4*)(panel_w + d * 8 + 4);
            float x = f[r];
            a[0] += x * w0.x; a[1] += x * w0.y; a[2] += x * w0.z; a[3] += x * w0.w;
            a[4] += x * w1.x; a[5] += x * w1.y; a[6] += x * w1.z; a[7] += x * w1.w;
        }
        reduce8(a);
        if (lane == 0) {
            float4 b0 = *(const float4*)(panel_b);
            float4 b1 = *(const float4*)(panel_b + 4);
            float4 o0 = make_float4(a[0] + b0.x, a[1] + b0.y, a[2] + b0.z, a[3] + b0.w);
            float4 o1 = make_float4(a[4] + b1.x, a[5] + b1.y, a[6] + b1.z, a[7] + b1.w);
            *(float4*)po = o0; *(float4*)(po + 4) = o1;
            *(float4*)dо = z4; *(float4*)(dо + 4) = z4;
            *(float4*)co = z4;
        }
        return;
    }

    // child token: DIALOG (2) or CHAR (3)
    int ps = g_parent_seq[b * NE + pidx[tk]];
    if (ps < 0) {
        if (lane == 0) {
            *(float4*)po = z4; *(float4*)(po + 4) = z4;
            *(float4*)dо = z4; *(float4*)(dо + 4) = z4;
            *(float4*)co = z4;
        }
        return;
    }

    float pf[NR];
    warp_feats(b * Sv + ps, b, lane, types, eidx, pidx, type_emb, index_emb,
               parent_emb, ln_g, ln_b, pf);

    if (t == 2) {  // DIALOG head: [f, pf] @ dialog_w(1536,8)
        float a[8] = {0.f, 0.f, 0.f, 0.f, 0.f, 0.f, 0.f, 0.f};
#pragma unroll
        for (int r = 0; r < NR; r++) {
            int d = lane + 32 * r;
            float4 w0 = *(const float4*)(dialog_w + d * 8);
            float4 w1 = *(const float4*)(dialog_w + d * 8 + 4);
            float4 v0 = *(const float4*)(dialog_w + (DD + d) * 8);
            float4 v1 = *(const float4*)(dialog_w + (DD + d) * 8 + 4);
            float x = f[r], y = pf[r];
            a[0] += x * w0.x + y * v0.x; a[1] += x * w0.y + y * v0.y;
            a[2] += x * w0.z + y * v0.z; a[3] += x * w0.w + y * v0.w;
            a[4] += x * w1.x + y * v1.x; a[5] += x * w1.y + y * v1.y;
            a[6] += x * w1.z + y * v1.z; a[7] += x * w1.w + y * v1.w;
        }
        reduce8(a);
        if (lane == 0) {
            float4 b0 = *(const float4*)(dialog_b);
            float4 b1 = *(const float4*)(dialog_b + 4);
            float4 o0 = make_float4(a[0] + b0.x, a[1] + b0.y, a[2] + b0.z, a[3] + b0.w);
            float4 o1 = make_float4(a[4] + b1.x, a[5] + b1.y, a[6] + b1.z, a[7] + b1.w);
            *(float4*)dо = o0; *(float4*)(dо + 4) = o1;
            *(float4*)po = z4; *(float4*)(po + 4) = z4;
            *(float4*)co = z4;
        }
    } else {  // CHAR head: [f, pf] @ char_w(1536,4)
        float a[4] = {0.f, 0.f, 0.f, 0.f};
#pragma unroll
        for (int r = 0; r < NR; r++) {
            int d = lane + 32 * r;
            float4 w0 = *(const float4*)(char_w + d * 4);
            float4 v0 = *(const float4*)(char_w + (DD + d) * 4);
            float x = f[r], y = pf[r];
            a[0] += x * w0.x + y * v0.x; a[1] += x * w0.y + y * v0.y;
            a[2] += x * w0.z + y * v0.z; a[3] += x * w0.w + y * v0.w;
        }
        reduce4(a);
        if (lane == 0) {
            float4 b0 = *(const float4*)(char_b);
            float4 oc = make_float4(a[0] + b0.x, a[1] + b0.y, a[2] + b0.z, a[3] + b0.w);
            *(float4*)co = oc;
            *(float4*)po = z4; *(float4*)(po + 4) = z4;
            *(float4*)dо = z4; *(float4*)(dо + 4) = z4;
        }
    }
}

// ---------------------------------------------------------------------------
extern "C" void kernel_launch(void* const* d_in, const int* in_sizes, int n_in,
                              void* d_out, int out_size) {
    const int*   types     = (const int*)d_in[0];
    const int*   eidx      = (const int*)d_in[1];
    const int*   pidx      = (const int*)d_in[2];
    const float* style_v   = (const float*)d_in[3];
    const float* type_emb  = (const float*)d_in[4];
    const float* index_emb = (const float*)d_in[5];
    const float* parent_emb= (const float*)d_in[6];
    const float* style_w   = (const float*)d_in[7];
    const float* style_b   = (const float*)d_in[8];
    const float* ln_g      = (const float*)d_in[9];
    const float* ln_b      = (const float*)d_in[10];
    const float* panel_w   = (const float*)d_in[11];
    const float* panel_b   = (const float*)d_in[12];
    const float* dialog_w  = (const float*)d_in[13];
    const float* dialog_b  = (const float*)d_in[14];
    const float* char_w    = (const float*)d_in[15];
    const float* char_b    = (const float*)d_in[16];

    int B = in_sizes[3] / 4;
    int S = in_sizes[0] / B;
    int total = B * S;

    float* out_panel  = (float*)d_out;
    float* out_dialog = out_panel + (size_t)total * 8;
    float* out_char   = out_dialog + (size_t)total * 8;

    setup_kernel<<<B, 256>>>(style_v, style_w, style_b, B);
    scan_kernel<<<(total + 255) / 256, 256>>>(types, eidx, S, total);

    int warps_per_block = 8;  // 256 threads
    int blocks = (total + warps_per_block - 1) / warps_per_block;
    main_kernel<<<blocks, 256>>>(types, eidx, pidx, type_emb, index_emb,
                                 parent_emb, ln_g, ln_b, panel_w, panel_b,
                                 dialog_w, dialog_b, char_w, char_b,
                                 out_panel, out_dialog, out_char, B, S);
}